// round 17
// baseline (speedup 1.0000x reference)
#include <cuda_runtime.h>
#include <cuda_fp16.h>
#include <cstdint>
#include <math.h>

// ---------------------------------------------------------------------------
// Problem constants
// ---------------------------------------------------------------------------
#define BF      32
#define TOK     256
#define DIMC    1280
#define HEADS   8
#define DH      160
#define CROSS   768
#define ESEQ    77
#define FRAMES  16
#define NROWS   (BF*TOK)          // 8192
#define ENCROWS (BF*ESEQ)         // 2464
#define FF_N    (2*4*DIMC)        // 10240
#define FF_I    (4*DIMC)          // 5120

// ---------------------------------------------------------------------------
// Scratch (device globals; no allocation allowed)
// ---------------------------------------------------------------------------
__device__ __align__(256) __half g_nh_h [NROWS*DIMC];
__device__ __align__(256) __half g_ao_h [NROWS*DIMC];
__device__ __align__(256) __half g_qkv_h[(size_t)NROWS*3*DIMC];
__device__ __align__(256) __half g_gg_h [(size_t)NROWS*FF_I];
__device__ __align__(256) __half g_kv_h [ENCROWS*2*DIMC];
__device__ __align__(256) __half g_enc_h[ENCROWS*CROSS];
__device__ float g_biasi[FF_N];
__device__ __align__(256) uint32_t g_wt[19005440];  // half2 k-pair-interleaved weights

// packed-weight offsets (uint32 = half2 units), layout [K/2][N]
#define OFF_W1QKV 0u
#define OFF_A1WO  2457600u
#define OFF_A2WQ  3276800u
#define OFF_W2KV  4096000u
#define OFF_A2WO  5079040u
#define OFF_FFW1  5898240u
#define OFF_FFW2  12451840u
#define OFF_WTQKV 15728640u
#define OFF_ATWO  18186240u

// ---------------------------------------------------------------------------
// Helpers
// ---------------------------------------------------------------------------
__device__ __forceinline__ uint32_t smem_u32(const void* p) {
    uint32_t a;
    asm("{ .reg .u64 t; cvta.to.shared.u64 t, %1; cvt.u32.u64 %0, t; }" : "=r"(a) : "l"(p));
    return a;
}

#define CPASYNC16(dst, src, sz) \
    asm volatile("cp.async.cg.shared.global [%0], [%1], 16, %2;" \
        :: "r"((uint32_t)(dst)), "l"(src), "r"((uint32_t)(sz)) : "memory")
#define CP_COMMIT() asm volatile("cp.async.commit_group;" ::: "memory")
#define CP_WAIT(n)  asm volatile("cp.async.wait_group %0;" :: "n"(n) : "memory")

#define MMA16816(c, a, b0, b1) \
    asm volatile( \
        "mma.sync.aligned.m16n8k16.row.col.f32.f16.f16.f32 " \
        "{%0,%1,%2,%3}, {%4,%5,%6,%7}, {%8,%9}, {%0,%1,%2,%3};" \
        : "+f"((c)[0]), "+f"((c)[1]), "+f"((c)[2]), "+f"((c)[3]) \
        : "r"((a)[0]), "r"((a)[1]), "r"((a)[2]), "r"((a)[3]), \
          "r"(b0), "r"(b1))

// temporal row map: t -> spatial s
__device__ __forceinline__ int t2s(int t) {
    int f = t & 15, tok = (t >> 4) & 255, b = t >> 12;
    return b * 4096 + f * 256 + tok;
}

// ---------------------------------------------------------------------------
// fp16 GEMM: C = A[M,K] @ B[K,N], fp32 accum. 64-K chunks, 3 stages.
// MODE 0: C fp32, +bias+res (PERM=1: write/res at t2s(row))
// MODE 1: C fp16, plain
// MODE 2: C fp16 [M, N/2], geglu over interleaved (p,g) pairs, + bias
// Requirements: K % 64 == 0, N % 128 == 0; M ragged OK.
// ---------------------------------------------------------------------------
#define STAGES        3
#define A_STG_BYTES   18432      // 128 rows * 144B (64 halves + 8 pad)
#define B_STG_BYTES   16384      // 32 pair-rows * 512B
#define GEMM_SMEM     (STAGES*(A_STG_BYTES+B_STG_BYTES))  // 104448

template<int MODE, int PERM>
__global__ void __launch_bounds__(256, 2)
gemm_f16(const __half* __restrict__ A, const uint32_t* __restrict__ B2,
         void* __restrict__ Cv, const float* __restrict__ bias,
         const float* __restrict__ res, int M, int N, int K)
{
    extern __shared__ __align__(16) char smem[];
    uint32_t aBase = smem_u32(smem);
    uint32_t bBase = aBase + STAGES * A_STG_BYTES;

    int tid  = threadIdx.x;
    int warp = tid >> 5, lane = tid & 31;
    int wm = warp & 3, wn = warp >> 2;
    int g  = lane >> 2, t4 = lane & 3;

    int num_m = (M + 127) >> 7, num_n = N >> 7;
    const int GM = 8;
    int npg = GM * num_n;
    int group = blockIdx.x / npg;
    int first = group * GM;
    int gsz = min(num_m - first, GM);
    int rem = blockIdx.x - group * npg;
    int m0 = (first + rem % gsz) << 7;
    int n0 = (rem / gsz) << 7;

    // ---- gmem load mapping (64-K chunk) ----
    // A: thread -> row tid&127, col-group tid>>7 (32 halves = 64B = 4x16B)
    int arow = tid & 127, acg = tid >> 7;
    bool aval = (m0 + arow) < M;
    const __half* aptr = A + (size_t)(m0 + arow) * K + acg * 32;
    uint32_t aDst = aBase + arow * 144 + acg * 64;
    // B: thread -> pair-row tid>>3 (0..31), eighth (tid&7) (64B = 4x16B chunks)
    int bpr = tid >> 3, bc8 = tid & 7;
    int Rb = (bpr & 1) + 4 * ((bpr >> 1) & 1);
    const uint32_t* bptr = B2 + (size_t)bpr * N + n0 + bc8 * 16;
    uint32_t bD[4];
#pragma unroll
    for (int i = 0; i < 4; i++)
        bD[i] = bBase + bpr * 512 + (((bc8 * 4 + i) + Rb) & 31) * 16;

    uint32_t aFrag = ((wm * 32 + (lane & 15)) * 72 + (lane >> 4) * 8) * 2;
    int Rf  = (t4 & 1) + 4 * ((t4 >> 1) & 1);
    int pc0 = ((16 * wn + 2 * g + Rf) & 31) * 16;
    int pc1 = ((16 * wn + 2 * g + 1 + Rf) & 31) * 16;

    float acc[2][8][4];
#pragma unroll
    for (int mi = 0; mi < 2; mi++)
#pragma unroll
        for (int ni = 0; ni < 8; ni++)
#pragma unroll
            for (int i = 0; i < 4; i++) acc[mi][ni][i] = 0.f;

    int KT = K >> 6;

#define LOAD_STAGE(kt, s)                                                     \
    do {                                                                      \
        const __half* _a = aptr + (size_t)(kt) * 64;                          \
        uint32_t _ad = aDst + (s) * A_STG_BYTES;                              \
        unsigned _sz = aval ? 16u : 0u;                                       \
        CPASYNC16(_ad,      _a,      _sz);                                    \
        CPASYNC16(_ad + 16, _a + 8,  _sz);                                    \
        CPASYNC16(_ad + 32, _a + 16, _sz);                                    \
        CPASYNC16(_ad + 48, _a + 24, _sz);                                    \
        const uint32_t* _b = bptr + (size_t)(kt) * 32 * N;                    \
        uint32_t _bs = (s) * B_STG_BYTES;                                     \
        CPASYNC16(bD[0] + _bs, _b,      16u);                                 \
        CPASYNC16(bD[1] + _bs, _b + 4,  16u);                                 \
        CPASYNC16(bD[2] + _bs, _b + 8,  16u);                                 \
        CPASYNC16(bD[3] + _bs, _b + 12, 16u);                                 \
    } while (0)

#pragma unroll
    for (int s = 0; s < STAGES - 1; s++) {
        if (s < KT) LOAD_STAGE(s, s);
        CP_COMMIT();
    }

    for (int kt = 0; kt < KT; kt++) {
        CP_WAIT(STAGES - 2);
        __syncthreads();

        int nk = kt + STAGES - 1;
        if (nk < KT) LOAD_STAGE(nk, nk % STAGES);
        CP_COMMIT();

        uint32_t astage = aBase + (kt % STAGES) * A_STG_BYTES + aFrag;
        uint32_t bstage = bBase + (kt % STAGES) * B_STG_BYTES;

#pragma unroll
        for (int ks = 0; ks < 4; ks++) {
            uint32_t af[2][4];
#pragma unroll
            for (int mi = 0; mi < 2; mi++) {
                uint32_t addr = astage + mi * (16 * 144) + ks * 32;
                asm volatile(
                    "ldmatrix.sync.aligned.m8n8.x4.shared.b16 {%0,%1,%2,%3}, [%4];"
                    : "=r"(af[mi][0]), "=r"(af[mi][1]),
                      "=r"(af[mi][2]), "=r"(af[mi][3])
                    : "r"(addr));
            }
            uint32_t r0 = bstage + (8 * ks + t4) * 512;
            uint32_t r1 = r0 + 2048;
            uint4 B00, B01, B10, B11;
            asm volatile("ld.shared.v4.b32 {%0,%1,%2,%3}, [%4];"
                : "=r"(B00.x), "=r"(B00.y), "=r"(B00.z), "=r"(B00.w) : "r"(r0 + pc0));
            asm volatile("ld.shared.v4.b32 {%0,%1,%2,%3}, [%4];"
                : "=r"(B01.x), "=r"(B01.y), "=r"(B01.z), "=r"(B01.w) : "r"(r0 + pc1));
            asm volatile("ld.shared.v4.b32 {%0,%1,%2,%3}, [%4];"
                : "=r"(B10.x), "=r"(B10.y), "=r"(B10.z), "=r"(B10.w) : "r"(r1 + pc0));
            asm volatile("ld.shared.v4.b32 {%0,%1,%2,%3}, [%4];"
                : "=r"(B11.x), "=r"(B11.y), "=r"(B11.z), "=r"(B11.w) : "r"(r1 + pc1));
            uint32_t b0a[8] = {B00.x, B00.y, B00.z, B00.w, B01.x, B01.y, B01.z, B01.w};
            uint32_t b1a[8] = {B10.x, B10.y, B10.z, B10.w, B11.x, B11.y, B11.z, B11.w};
#pragma unroll
            for (int ni = 0; ni < 8; ni++) {
#pragma unroll
                for (int mi = 0; mi < 2; mi++)
                    MMA16816(acc[mi][ni], af[mi], b0a[ni], b1a[ni]);
            }
        }
    }
#undef LOAD_STAGE

    int colb = n0 + wn * 64 + 16 * t4;
#define ACCV(s, hh) ((s) < 8 ? acc[mi][(s)][(hh) ? 2 : 0] : acc[mi][(s) - 8][(hh) ? 3 : 1])

    if (MODE == 0) {
        float* C = (float*)Cv;
        float4 bv[4];
#pragma unroll
        for (int q2 = 0; q2 < 4; q2++)
            bv[q2] = *(const float4*)(bias + colb + 4 * q2);
#pragma unroll
        for (int mi = 0; mi < 2; mi++) {
            int row0 = m0 + wm * 32 + mi * 16 + g;
#pragma unroll
            for (int h = 0; h < 2; h++) {
                int row = row0 + h * 8;
                if (row < M) {
                    int grow = PERM ? t2s(row) : row;
                    size_t base = (size_t)grow * N + colb;
#pragma unroll
                    for (int q2 = 0; q2 < 4; q2++) {
                        float4 o;
                        float* s0 = &o.x;
#pragma unroll
                        for (int e = 0; e < 4; e++)
                            s0[e] = ACCV(4 * q2 + e, h);
                        float4 rv = *(const float4*)(res + base + 4 * q2);
                        const float* bb = &bv[q2].x;
                        o.x += bb[0] + rv.x; o.y += bb[1] + rv.y;
                        o.z += bb[2] + rv.z; o.w += bb[3] + rv.w;
                        *(float4*)(C + base + 4 * q2) = o;
                    }
                }
            }
        }
    } else if (MODE == 1) {
        __half* C = (__half*)Cv;
#pragma unroll
        for (int mi = 0; mi < 2; mi++) {
            int row0 = m0 + wm * 32 + mi * 16 + g;
#pragma unroll
            for (int h = 0; h < 2; h++) {
                int row = row0 + h * 8;
                if (row < M) {
                    __half* dst = C + (size_t)row * N + colb;
#pragma unroll
                    for (int q2 = 0; q2 < 2; q2++) {
                        uint4 u;
                        __half2 h0 = __floats2half2_rn(ACCV(8*q2+0, h), ACCV(8*q2+1, h));
                        __half2 h1 = __floats2half2_rn(ACCV(8*q2+2, h), ACCV(8*q2+3, h));
                        __half2 h2 = __floats2half2_rn(ACCV(8*q2+4, h), ACCV(8*q2+5, h));
                        __half2 h3 = __floats2half2_rn(ACCV(8*q2+6, h), ACCV(8*q2+7, h));
                        u.x = *reinterpret_cast<uint32_t*>(&h0);
                        u.y = *reinterpret_cast<uint32_t*>(&h1);
                        u.z = *reinterpret_cast<uint32_t*>(&h2);
                        u.w = *reinterpret_cast<uint32_t*>(&h3);
                        *(uint4*)(dst + 8 * q2) = u;
                    }
                }
            }
        }
    } else {
        __half* C = (__half*)Cv;
        int No = N >> 1;
        float bvf[16];
#pragma unroll
        for (int q2 = 0; q2 < 4; q2++)
            *(float4*)(bvf + 4 * q2) = *(const float4*)(bias + colb + 4 * q2);
#pragma unroll
        for (int mi = 0; mi < 2; mi++) {
            int row0 = m0 + wm * 32 + mi * 16 + g;
#pragma unroll
            for (int h = 0; h < 2; h++) {
                int row = row0 + h * 8;
                if (row < M) {
                    float ov[8];
#pragma unroll
                    for (int e = 0; e < 8; e++) {
                        float p  = ACCV(2 * e, h)     + bvf[2 * e];
                        float gg = ACCV(2 * e + 1, h) + bvf[2 * e + 1];
                        float gel = 0.5f * gg * (1.f + erff(gg * 0.70710678118654752f));
                        ov[e] = p * gel;
                    }
                    uint4 u;
                    __half2 h0 = __floats2half2_rn(ov[0], ov[1]);
                    __half2 h1 = __floats2half2_rn(ov[2], ov[3]);
                    __half2 h2 = __floats2half2_rn(ov[4], ov[5]);
                    __half2 h3 = __floats2half2_rn(ov[6], ov[7]);
                    u.x = *reinterpret_cast<uint32_t*>(&h0);
                    u.y = *reinterpret_cast<uint32_t*>(&h1);
                    u.z = *reinterpret_cast<uint32_t*>(&h2);
                    u.w = *reinterpret_cast<uint32_t*>(&h3);
                    *(uint4*)(C + (size_t)row * No + (colb >> 1)) = u;
                }
            }
        }
    }
#undef ACCV
}

// ---------------------------------------------------------------------------
// Fused prologue packing: 13 plain packs + enc f2h in ONE kernel.
// ---------------------------------------------------------------------------
struct PackParams { const float* s[13]; const float* enc; };

__constant__ int PJ_base[15]    = {0, 204800, 409600, 614400, 819200, 1024000,
                                   1146880, 1269760, 1474560, 2293760, 2498560,
                                   2703360, 2908160, 3112960, 3349504};
__constant__ int PJ_N[14]       = {1280,1280,1280,1280,1280,1280,1280,1280,1280,
                                   1280,1280,1280,1280, 0};
__constant__ int PJ_dstride[14] = {3840,3840,3840,1280,1280,2560,2560,1280,1280,
                                   3840,3840,3840,1280, 0};
__constant__ int PJ_coff[14]    = {0,1280,2560,0,0,0,1280,0,0,0,1280,2560,0, 0};
__constant__ unsigned PJ_doff[14] = {OFF_W1QKV,OFF_W1QKV,OFF_W1QKV,OFF_A1WO,
                                     OFF_A2WQ,OFF_W2KV,OFF_W2KV,OFF_A2WO,
                                     OFF_FFW2,OFF_WTQKV,OFF_WTQKV,OFF_WTQKV,
                                     OFF_ATWO, 0};

__global__ void pack_all(PackParams pp, uint32_t* __restrict__ wt,
                         __half* __restrict__ ench)
{
    int idx = blockIdx.x * 256 + threadIdx.x;
    if (idx >= 3349504) return;
    int job = 0;
#pragma unroll
    for (int j = 1; j < 15; j++) job += (idx >= PJ_base[j]);
    int local = idx - PJ_base[job];

    if (job == 13) {
        int i = local * 8;
        float4 a = *(const float4*)(pp.enc + i);
        float4 b = *(const float4*)(pp.enc + i + 4);
        __half2 h0 = __floats2half2_rn(a.x, a.y);
        __half2 h1 = __floats2half2_rn(a.z, a.w);
        __half2 h2 = __floats2half2_rn(b.x, b.y);
        __half2 h3 = __floats2half2_rn(b.z, b.w);
        uint4 o;
        o.x = *reinterpret_cast<uint32_t*>(&h0);
        o.y = *reinterpret_cast<uint32_t*>(&h1);
        o.z = *reinterpret_cast<uint32_t*>(&h2);
        o.w = *reinterpret_cast<uint32_t*>(&h3);
        *(uint4*)(ench + i) = o;
        return;
    }

    const float* src = pp.s[job];
    int N = PJ_N[job];
    int npc = N >> 2;
    int kp = local / npc, n4 = (local - kp * npc) * 4;
    const float* r0 = src + (size_t)(2 * kp) * N + n4;
    const float* r1 = r0 + N;
    float4 lo = *(const float4*)r0, hi = *(const float4*)r1;
    __half2 h0 = __floats2half2_rn(lo.x, hi.x);
    __half2 h1 = __floats2half2_rn(lo.y, hi.y);
    __half2 h2 = __floats2half2_rn(lo.z, hi.z);
    __half2 h3 = __floats2half2_rn(lo.w, hi.w);
    uint4 o;
    o.x = *reinterpret_cast<uint32_t*>(&h0);
    o.y = *reinterpret_cast<uint32_t*>(&h1);
    o.z = *reinterpret_cast<uint32_t*>(&h2);
    o.w = *reinterpret_cast<uint32_t*>(&h3);
    *(uint4*)(wt + PJ_doff[job] + (size_t)kp * PJ_dstride[job] + PJ_coff[job] + n4) = o;
}

__global__ void pack_ffn1(const float* __restrict__ src, uint32_t* __restrict__ dst,
                          const float* __restrict__ b, float* __restrict__ bi)
{
    const int HALF = FF_I;
    const int ILV_BLOCKS = 6400;
    if (blockIdx.x >= ILV_BLOCKS) {
        int j = (blockIdx.x - ILV_BLOCKS) * 256 + threadIdx.x;
        if (j < FF_I) { bi[2*j] = b[j]; bi[2*j + 1] = b[FF_I + j]; }
        return;
    }
    int idx = blockIdx.x * 256 + threadIdx.x;
    int jpc = HALF / 2;
    int kp = idx / jpc, j0 = (idx - kp * jpc) * 2;
    const float* r0 = src + (size_t)(2 * kp) * FF_N;
    const float* r1 = r0 + FF_N;
    float2 p0 = *(const float2*)(r0 + j0);
    float2 p1 = *(const float2*)(r1 + j0);
    float2 g0 = *(const float2*)(r0 + HALF + j0);
    float2 g1 = *(const float2*)(r1 + HALF + j0);
    __half2 hp0 = __floats2half2_rn(p0.x, p1.x);
    __half2 hg0 = __floats2half2_rn(g0.x, g1.x);
    __half2 hp1 = __floats2half2_rn(p0.y, p1.y);
    __half2 hg1 = __floats2half2_rn(g0.y, g1.y);
    uint4 o;
    o.x = *reinterpret_cast<uint32_t*>(&hp0);
    o.y = *reinterpret_cast<uint32_t*>(&hg0);
    o.z = *reinterpret_cast<uint32_t*>(&hp1);
    o.w = *reinterpret_cast<uint32_t*>(&hg1);
    *(uint4*)(dst + (size_t)kp * FF_N + 2 * j0) = o;
}

// ---------------------------------------------------------------------------
// LayerNorm (fp32 in, fp16 out). perm=1: read spatial row t2s(t).
// ---------------------------------------------------------------------------
__global__ __launch_bounds__(128)
void ln_kernel(const float* __restrict__ x, const float* __restrict__ w,
               const float* __restrict__ b, __half* __restrict__ y, int perm)
{
    int row = blockIdx.x;
    int srow = perm ? t2s(row) : row;
    const float* xr = x + (size_t)srow * DIMC;
    __half*      yr = y + (size_t)row * DIMC;
    int tid = threadIdx.x;

    float v[10];
    float s = 0.f, ss = 0.f;
#pragma unroll
    for (int i = 0; i < 10; i++) {
        float t = xr[tid + i*128];
        v[i] = t; s += t; ss += t*t;
    }
#pragma unroll
    for (int off = 16; off; off >>= 1) {
        s  += __shfl_xor_sync(0xffffffffu, s,  off);
        ss += __shfl_xor_sync(0xffffffffu, ss, off);
    }
    __shared__ float sh[8];
    int warp = tid >> 5;
    if ((tid & 31) == 0) { sh[warp] = s; sh[4+warp] = ss; }
    __syncthreads();
    s  = sh[0] + sh[1] + sh[2] + sh[3];
    ss = sh[4] + sh[5] + sh[6] + sh[7];
    float mean = s * (1.f/1280.f);
    float var  = ss * (1.f/1280.f) - mean*mean;
    float rstd = rsqrtf(var + 1e-5f);
#pragma unroll
    for (int i = 0; i < 10; i++) {
        int c = tid + i*128;
        yr[c] = __float2half_rn((v[i] - mean) * rstd * w[c] + b[c]);
    }
}

// ---------------------------------------------------------------------------
// Tensor-core flash attention (unchanged)
// ---------------------------------------------------------------------------
#define QPAD 168

__global__ void __launch_bounds__(128, 3)
attn_tc(const __half* __restrict__ Q, const __half* __restrict__ K,
        const __half* __restrict__ V, __half* __restrict__ O,
        int Sq, int Sk, long q_bs, long kv_bs, long o_bs,
        int ldq, int ldkv, int ldo, int sparse, float scale)
{
    __shared__ __half Qs[64][QPAD];
    __shared__ __half Ks[32][QPAD];
    __shared__ __half Vs[32][QPAD];

    int batch = blockIdx.z, head = blockIdx.y;
    int q0  = blockIdx.x * 64;
    int tid = threadIdx.x;
    int wp  = tid >> 5, lane = tid & 31;
    int g   = lane >> 2, t4 = lane & 3;

    uint32_t qsB = smem_u32(&Qs[0][0]);
    uint32_t ksB = smem_u32(&Ks[0][0]);
    uint32_t vsB = smem_u32(&Vs[0][0]);

    {
        int row = tid >> 1, half16 = (tid & 1) * 10;
        bool valid = (q0 + row) < Sq;
        const uint4* src = (const uint4*)(Q + (size_t)batch * q_bs
                          + (size_t)(q0 + (valid ? row : 0)) * ldq + head * DH);
        uint4* dst = (uint4*)&Qs[row][0];
#pragma unroll
        for (int i = 0; i < 10; i++) {
            uint4 u = valid ? src[half16 + i] : make_uint4(0,0,0,0);
            dst[half16 + i] = u;
        }
    }
    __syncthreads();

    uint32_t qf[10][4];
    {
        uint32_t base = qsB + ((16*wp + (lane & 15)) * QPAD + (lane >> 4) * 8) * 2;
#pragma unroll
        for (int d = 0; d < 10; d++) {
            asm volatile(
                "ldmatrix.sync.aligned.m8n8.x4.shared.b16 {%0,%1,%2,%3}, [%4];"
                : "=r"(qf[d][0]), "=r"(qf[d][1]), "=r"(qf[d][2]), "=r"(qf[d][3])
                : "r"(base + d * 32));
        }
    }
    __syncthreads();

    float o[20][4];
#pragma unroll
    for (int w = 0; w < 20; w++)
#pragma unroll
        for (int c = 0; c < 4; c++) o[w][c] = 0.f;
    float m0 = -1e30f, m1 = -1e30f, l0 = 0.f, l1 = 0.f;

    int selK = lane >> 3;
    int krow = 8 * (selK >> 1) + (lane & 7);
    int koff = 16 * (selK & 1);
    int vkey = 8 * (selK & 1) + (lane & 7);
    int vwin = (selK >> 1);

    int ntiles = (Sk + 31) >> 5;
    for (int kt = 0; kt < ntiles; kt++) {
        {
            int row = tid >> 2, c4i = (tid & 3) * 5;
            int j = kt * 32 + row;
            const uint4* kp = nullptr; const uint4* vp = nullptr;
            if (j < Sk) {
                size_t off;
                if (sparse) {
                    int bb = batch >> 4, f = batch & 15;
                    int srcf = (j < 256) ? 0 : ((f > 0) ? (f - 1) : 0);
                    int jr2  = (j < 256) ? j : (j - 256);
                    off = (size_t)((bb*16 + srcf) * 256 + jr2) * ldkv + head * DH;
                } else {
                    off = (size_t)batch * kv_bs + (size_t)j * ldkv + head * DH;
                }
                kp = (const uint4*)(K + off); vp = (const uint4*)(V + off);
            }
            uint4* kd = (uint4*)&Ks[row][0];
            uint4* vd = (uint4*)&Vs[row][0];
#pragma unroll
            for (int i = 0; i < 5; i++) {
                uint4 ku = kp ? kp[c4i + i] : make_uint4(0,0,0,0);
                uint4 vu = vp ? vp[c4i + i] : make_uint4(0,0,0,0);
                kd[c4i + i] = ku;
                vd[c4i + i] = vu;
            }
        }
        __syncthreads();

        float s[4][4];
#pragma unroll
        for (int j = 0; j < 4; j++)
#pragma unroll
            for (int c = 0; c < 4; c++) s[j][c] = 0.f;
#pragma unroll
        for (int d = 0; d < 10; d++) {
            uint32_t kb[4], kb2[4];
            uint32_t a0 = ksB + (krow * QPAD) * 2 + koff + 32 * d;
            asm volatile(
                "ldmatrix.sync.aligned.m8n8.x4.shared.b16 {%0,%1,%2,%3}, [%4];"
                : "=r"(kb[0]), "=r"(kb[1]), "=r"(kb[2]), "=r"(kb[3]) : "r"(a0));
            uint32_t a1 = a0 + 16 * QPAD * 2;
            asm volatile(
                "ldmatrix.sync.aligned.m8n8.x4.shared.b16 {%0,%1,%2,%3}, [%4];"
                : "=r"(kb2[0]), "=r"(kb2[1]), "=r"(kb2[2]), "=r"(kb2[3]) : "r"(a1));
            MMA16816(s[0], qf[d], kb[0],  kb[1]);
            MMA16816(s[1], qf[d], kb[2],  kb[3]);
            MMA16816(s[2], qf[d], kb2[0], kb2[1]);
            MMA16816(s[3], qf[d], kb2[2], kb2[3]);
        }

        int kbase = kt * 32;
        float tm0 = -1e30f, tm1 = -1e30f;
#pragma unroll
        for (int j = 0; j < 4; j++) {
            int k0 = kbase + 8*j + 2*t4;
            bool v0 = k0 < Sk, v1 = (k0 + 1) < Sk;
            s[j][0] = v0 ? s[j][0] * scale : -1e30f;
            s[j][1] = v1 ? s[j][1] * scale : -1e30f;
            s[j][2] = v0 ? s[j][2] * scale : -1e30f;
            s[j][3] = v1 ? s[j][3] * scale : -1e30f;
            tm0 = fmaxf(tm0, fmaxf(s[j][0], s[j][1]));
            tm1 = fmaxf(tm1, fmaxf(s[j][2], s[j][3]));
        }
        tm0 = fmaxf(tm0, __shfl_xor_sync(0xffffffffu, tm0, 1));
        tm0 = fmaxf(tm0, __shfl_xor_sync(0xffffffffu, tm0, 2));
        tm1 = fmaxf(tm1, __shfl_xor_sync(0xffffffffu, tm1, 1));
        tm1 = fmaxf(tm1, __shfl_xor_sync(0xffffffffu, tm1, 2));

        if (tm0 > m0 || tm1 > m1) {
            float nm0 = fmaxf(m0, tm0), nm1 = fmaxf(m1, tm1);
            float a0 = __expf(m0 - nm0), a1 = __expf(m1 - nm1);
            m0 = nm0; m1 = nm1;
            l0 *= a0; l1 *= a1;
#pragma unroll
            for (int w = 0; w < 20; w++) {
                o[w][0] *= a0; o[w][1] *= a0;
                o[w][2] *= a1; o[w][3] *= a1;
            }
        }

        uint32_t plo[4], phi[4];
#pragma unroll
        for (int j = 0; j < 4; j++) {
            float e0 = __expf(s[j][0] - m0), e1 = __expf(s[j][1] - m0);
            float e2 = __expf(s[j][2] - m1), e3 = __expf(s[j][3] - m1);
            l0 += e0 + e1; l1 += e2 + e3;
            __half2 hl = __floats2half2_rn(e0, e1);
            __half2 hh = __floats2half2_rn(e2, e3);
            plo[j] = *reinterpret_cast<uint32_t*>(&hl);
            phi[j] = *reinterpret_cast<uint32_t*>(&hh);
        }

#pragma unroll
        for (int kk = 0; kk < 2; kk++) {
            uint32_t pa[4] = {plo[2*kk], phi[2*kk], plo[2*kk+1], phi[2*kk+1]};
#pragma unroll
            for (int w2 = 0; w2 < 10; w2++) {
                uint32_t vb[4];
                uint32_t a = vsB + ((16*kk + vkey) * QPAD + (2*w2 + vwin) * 8) * 2;
                asm volatile(
                    "ldmatrix.sync.aligned.m8n8.x4.trans.shared.b16 {%0,%1,%2,%3}, [%4];"
                    : "=r"(vb[0]), "=r"(vb[1]), "=r"(vb[2]), "=r"(vb[3]) : "r"(a));
                MMA16816(o[2*w2],     pa, vb[0], vb[1]);
                MMA16816(o[2*w2 + 1], pa, vb[2], vb[3]);
            }
        }
        __syncthreads();
    }

    l0 += __shfl_xor_sync(0xffffffffu, l0, 1);
    l0 += __shfl_xor_sync(0xffffffffu, l0, 2);
    l1 += __shfl_xor_sync(0xffffffffu, l1, 1);
    l1 += __shfl_xor_sync(0xffffffffu, l1, 2);
    float inv0 = 1.f / l0, inv1 = 1.f / l1;

    int row0 = q0 + 16*wp + g;
    int row1 = row0 + 8;
    __half* ob = O + (size_t)batch * o_bs + head * DH + 2 * t4;
#pragma unroll
    for (int w = 0; w < 20; w++) {
        if (row0 < Sq) {
            __half2 hv = __floats2half2_rn(o[w][0] * inv0, o[w][1] * inv0);
            *(__half2*)(ob + (size_t)row0 * ldo + 8 * w) = hv;
        }
        if (row1 < Sq) {
            __half2 hv = __floats2half2_rn(o[w][2] * inv1, o[w][3] * inv1);
            *(__half2*)(ob + (size_t)row1 * ldo + 8 * w) = hv;
        }
    }
}

// ---------------------------------------------------------------------------
// Host launcher
// ---------------------------------------------------------------------------
template<int MODE, int PERM>
static void launch_gemm(const __half* A, const uint32_t* B2, void* C,
                        const float* bias, const float* res,
                        int M, int N, int K)
{
    static bool attr_set = false;
    if (!attr_set) {
        cudaFuncSetAttribute(gemm_f16<MODE, PERM>,
            cudaFuncAttributeMaxDynamicSharedMemorySize, GEMM_SMEM);
        attr_set = true;
    }
    int nm = (M + 127) / 128, nn = N / 128;
    gemm_f16<MODE, PERM><<<nm * nn, 256, GEMM_SMEM>>>(A, B2, C, bias, res, M, N, K);
}

extern "C" void kernel_launch(void* const* d_in, const int* in_sizes, int n_in,
                              void* d_out, int out_size)
{
    const float* hid  = (const float*)d_in[0];
    const float* enc  = (const float*)d_in[1];
    const float* n1w  = (const float*)d_in[2];
    const float* n1b  = (const float*)d_in[3];
    const float* a1wq = (const float*)d_in[4];
    const float* a1wk = (const float*)d_in[5];
    const float* a1wv = (const float*)d_in[6];
    const float* a1wo = (const float*)d_in[7];
    const float* a1bo = (const float*)d_in[8];
    const float* n2w  = (const float*)d_in[9];
    const float* n2b  = (const float*)d_in[10];
    const float* a2wq = (const float*)d_in[11];
    const float* a2wk = (const float*)d_in[12];
    const float* a2wv = (const float*)d_in[13];
    const float* a2wo = (const float*)d_in[14];
    const float* a2bo = (const float*)d_in[15];
    const float* n3w  = (const float*)d_in[16];
    const float* n3b  = (const float*)d_in[17];
    const float* ffw1 = (const float*)d_in[18];
    const float* ffb1 = (const float*)d_in[19];
    const float* ffw2 = (const float*)d_in[20];
    const float* ffb2 = (const float*)d_in[21];
    const float* ntw  = (const float*)d_in[22];
    const float* ntb  = (const float*)d_in[23];
    const float* atwq = (const float*)d_in[24];
    const float* atwk = (const float*)d_in[25];
    const float* atwv = (const float*)d_in[26];
    const float* atwo = (const float*)d_in[27];
    const float* atbo = (const float*)d_in[28];

    float* out = (float*)d_out;

    __half *nh, *ao, *qkv, *gg, *kvh, *ench;
    float *biasi;
    uint32_t* wt;
    cudaGetSymbolAddress((void**)&nh,   g_nh_h);
    cudaGetSymbolAddress((void**)&ao,   g_ao_h);
    cudaGetSymbolAddress((void**)&qkv,  g_qkv_h);
    cudaGetSymbolAddress((void**)&gg,   g_gg_h);
    cudaGetSymbolAddress((void**)&kvh,  g_kv_h);
    cudaGetSymbolAddress((void**)&ench, g_enc_h);
    cudaGetSymbolAddress((void**)&biasi,g_biasi);
    cudaGetSymbolAddress((void**)&wt,   g_wt);

    const float scale = 0.07905694150420949f;   // 160^-0.5

    // ---- prologue: 2 launches ----
    {
        PackParams pp;
        pp.s[0] = a1wq; pp.s[1] = a1wk; pp.s[2] = a1wv; pp.s[3] = a1wo;
        pp.s[4] = a2wq; pp.s[5] = a2wk; pp.s[6] = a2wv; pp.s[7] = a2wo;
        pp.s[8] = ffw2; pp.s[9] = atwq; pp.s[10] = atwk; pp.s[11] = atwv;
        pp.s[12] = atwo; pp.enc = enc;
        pack_all<<<(3349504 + 255) / 256, 256>>>(pp, wt, ench);
        pack_ffn1<<<6400 + 20, 256>>>(ffw1, wt + OFF_FFW1, ffb1, biasi);
    }

    const int QKV = 3 * DIMC;     // 3840
    const int KV2 = 2 * DIMC;     // 2560

    // ---- attn1: sparse-causal self-attention ----
    ln_kernel<<<NROWS, 128>>>(hid, n1w, n1b, nh, 0);
    launch_gemm<1,0>(nh, wt + OFF_W1QKV, qkv, nullptr, nullptr, NROWS, QKV, DIMC);
    attn_tc<<<dim3(4, HEADS, BF), 128>>>(
        qkv, qkv + DIMC, qkv + 2*DIMC, ao,
        TOK, 2*TOK, (long)TOK*QKV, 0, (long)TOK*DIMC,
        QKV, QKV, DIMC, 1, scale);
    launch_gemm<0,0>(ao, wt + OFF_A1WO, out, a1bo, hid, NROWS, DIMC, DIMC);

    // ---- attn2: cross-attention ----
    ln_kernel<<<NROWS, 128>>>(out, n2w, n2b, nh, 0);
    launch_gemm<1,0>(nh,   wt + OFF_A2WQ, qkv, nullptr, nullptr, NROWS,   DIMC, DIMC);
    launch_gemm<1,0>(ench, wt + OFF_W2KV, kvh, nullptr, nullptr, ENCROWS, KV2,  CROSS);
    attn_tc<<<dim3(4, HEADS, BF), 128>>>(
        qkv, kvh, kvh + DIMC, ao,
        TOK, ESEQ, (long)TOK*DIMC, (long)ESEQ*KV2, (long)TOK*DIMC,
        DIMC, KV2, DIMC, 0, scale);
    launch_gemm<0,0>(ao, wt + OFF_A2WO, out, a2bo, out, NROWS, DIMC, DIMC);

    // ---- geglu FFN (geglu fused into ffn1 epilogue) ----
    ln_kernel<<<NROWS, 128>>>(out, n3w, n3b, nh, 0);
    launch_gemm<2,0>(nh, wt + OFF_FFW1, gg, biasi, nullptr, NROWS, FF_N, DIMC);
    launch_gemm<0,0>(gg, wt + OFF_FFW2, out, ffb2, out, NROWS, DIMC, FF_I);

    // ---- temporal self-attention (transposes fused via row permutation) ----
    ln_kernel<<<NROWS, 128>>>(out, ntw, ntb, nh, 1);
    launch_gemm<1,0>(nh, wt + OFF_WTQKV, qkv, nullptr, nullptr, NROWS, QKV, DIMC);
    attn_tc<<<dim3(1, HEADS, 2*TOK), 128>>>(
        qkv, qkv + DIMC, qkv + 2*DIMC, ao,
        FRAMES, FRAMES, (long)FRAMES*QKV, (long)FRAMES*QKV, (long)FRAMES*DIMC,
        QKV, QKV, DIMC, 0, scale);
    launch_gemm<0,1>(ao, wt + OFF_ATWO, out, atbo, out, NROWS, DIMC, DIMC);
}